// round 1
// baseline (speedup 1.0000x reference)
#include <cuda_runtime.h>
#include <cuda_bf16.h>
#include <cstdint>

#define B_   32
#define T_   8
#define BT_  256
#define H_   14
#define W_   14
#define P_   196
#define L_   197
#define C_   768
#define CA_  384
#define M_   (BT_*P_)   // 50176

// ---- scratch (static __device__ arrays: allocation-free) ----
__device__ __nv_bfloat16 g_Abf[(size_t)M_ * C_];   // x tokens, bf16   (77 MB)
__device__ __nv_bfloat16 g_W1b[CA_ * C_];          // W1 bf16
__device__ __nv_bfloat16 g_W2b[C_ * CA_];          // W2 bf16
__device__ __nv_bfloat16 g_h[(size_t)M_ * CA_];    // fc1 out          (38.5 MB)
__device__ __nv_bfloat16 g_g[(size_t)M_ * CA_];    // conv out         (38.5 MB)

// ---------------- helpers ----------------
__device__ __forceinline__ uint32_t smem_u32(const void* p) {
    return (uint32_t)__cvta_generic_to_shared(p);
}

__device__ __forceinline__ void cp16(void* sdst, const void* gsrc) {
    uint32_t d = smem_u32(sdst);
    asm volatile("cp.async.cg.shared.global [%0], [%1], 16;\n" :: "r"(d), "l"(gsrc));
}

__device__ __forceinline__ void ldsm4(uint32_t& r0, uint32_t& r1, uint32_t& r2, uint32_t& r3, uint32_t addr) {
    asm volatile("ldmatrix.sync.aligned.m8n8.x4.shared.b16 {%0,%1,%2,%3}, [%4];\n"
                 : "=r"(r0), "=r"(r1), "=r"(r2), "=r"(r3) : "r"(addr));
}
__device__ __forceinline__ void ldsm2(uint32_t& r0, uint32_t& r1, uint32_t addr) {
    asm volatile("ldmatrix.sync.aligned.m8n8.x2.shared.b16 {%0,%1}, [%2];\n"
                 : "=r"(r0), "=r"(r1) : "r"(addr));
}

__device__ __forceinline__ void mma_bf16(float (&d)[4], const uint32_t (&a)[4], const uint32_t (&b)[2]) {
    asm volatile(
        "mma.sync.aligned.m16n8k16.row.col.f32.bf16.bf16.f32 "
        "{%0,%1,%2,%3}, {%4,%5,%6,%7}, {%8,%9}, {%0,%1,%2,%3};\n"
        : "+f"(d[0]), "+f"(d[1]), "+f"(d[2]), "+f"(d[3])
        : "r"(a[0]), "r"(a[1]), "r"(a[2]), "r"(a[3]), "r"(b[0]), "r"(b[1]));
}

// ---------------- prep kernels ----------------
__global__ void prep_weights(const float* __restrict__ W1, const float* __restrict__ W2) {
    int i = blockIdx.x * 256 + threadIdx.x;   // grid covers exactly CA_*C_ = 294912
    g_W1b[i] = __float2bfloat16(W1[i]);
    g_W2b[i] = __float2bfloat16(W2[i]);
}

// gather non-CLS tokens of x -> dense bf16 A [M_, C_]
__global__ void prep_x(const float4* __restrict__ x4) {
    size_t i = (size_t)blockIdx.x * 256 + threadIdx.x;   // < M_*C_/4 = 9,633,792
    if (i >= (size_t)M_ * C_ / 4) return;
    size_t e = i * 4;
    int m = (int)(e / C_);
    int k = (int)(e - (size_t)m * C_);
    int bt = m / P_;
    size_t src = ((size_t)(m + bt + 1) * C_ + k) >> 2;
    float4 v = __ldg(&x4[src]);
    __nv_bfloat162* dst = (__nv_bfloat162*)(g_Abf + e);
    dst[0] = __floats2bfloat162_rn(v.x, v.y);
    dst[1] = __floats2bfloat162_rn(v.z, v.w);
}

__global__ void cls_copy(const float4* __restrict__ x4, float4* __restrict__ o4) {
    int i = blockIdx.x * 256 + threadIdx.x;  // grid covers exactly BT_*C_/4 = 49152
    int bt = i / (C_ / 4);
    int j = i - bt * (C_ / 4);
    size_t off = (size_t)bt * L_ * (C_ / 4) + j;
    o4[off] = x4[off];
}

// ---------------- GEMM (bf16 mma.sync, cp.async 4-stage) ----------------
// C[m,n] = sum_k A[m,k]*B[n,k]  (A row-major [M,K], B row-major [N,K] = weights)
// MODE 0: A=g_Abf K=768 -> g_h bf16 (+b1)
// MODE 1: A=g_g   K=384 -> out fp32 (+b2 + x residual, skewed rows)
#define GBM 128
#define GBN 128
#define GBK 32
#define GSTAGES 4
#define GPITCH 40            // bf16 elems per smem row (32 + 8 pad)
#define GSTAGE_BYTES (2 * GBM * GPITCH * 2)   // A tile + B tile = 20480

template <int MODE>
__global__ __launch_bounds__(256)
void gemm_k(const float* __restrict__ bias,
            const float* __restrict__ xres,
            float* __restrict__ outf) {
    constexpr int KD = (MODE == 0) ? C_ : CA_;
    constexpr int NK = KD / GBK;
    const __nv_bfloat16* __restrict__ A  = (MODE == 0) ? g_Abf : g_g;
    const __nv_bfloat16* __restrict__ Bw = (MODE == 0) ? g_W1b : g_W2b;

    extern __shared__ char smem[];
    const int tid  = threadIdx.x;
    const int lane = tid & 31;
    const int warp = tid >> 5;
    const int bm = blockIdx.y * GBM;
    const int bn = blockIdx.x * GBN;
    const int wm0 = (warp >> 2) * 64;
    const int wn0 = (warp & 3) * 32;

    // global->smem copy slots: 512 x 16B per tile half (A then B)
    const int rA0 = tid >> 2, cA0 = tid & 3;
    const int rA1 = (tid + 256) >> 2, cA1 = (tid + 256) & 3;

    auto issue = [&](int kt) {
        const int k0 = kt * GBK;
        char* st = smem + (size_t)(kt & (GSTAGES - 1)) * GSTAGE_BYTES;
        // A half at st, B half at st + 10240
        cp16(st + rA0 * 80 + cA0 * 16, A + (size_t)(bm + rA0) * KD + k0 + cA0 * 8);
        cp16(st + rA1 * 80 + cA1 * 16, A + (size_t)(bm + rA1) * KD + k0 + cA1 * 8);
        char* stB = st + GBM * GPITCH * 2;
        cp16(stB + rA0 * 80 + cA0 * 16, Bw + (size_t)(bn + rA0) * KD + k0 + cA0 * 8);
        cp16(stB + rA1 * 80 + cA1 * 16, Bw + (size_t)(bn + rA1) * KD + k0 + cA1 * 8);
    };

    #pragma unroll
    for (int s = 0; s < GSTAGES - 1; ++s) {
        issue(s);
        asm volatile("cp.async.commit_group;\n" ::: "memory");
    }

    float acc[4][4][4];
    #pragma unroll
    for (int mt = 0; mt < 4; ++mt)
        #pragma unroll
        for (int nt = 0; nt < 4; ++nt)
            #pragma unroll
            for (int i = 0; i < 4; ++i) acc[mt][nt][i] = 0.0f;

    const int a_row = lane & 15;
    const int a_col = (lane >> 4) << 3;
    const int b_row = lane & 7;
    const int b_col = ((lane >> 3) & 1) << 3;

    for (int kt = 0; kt < NK; ++kt) {
        asm volatile("cp.async.wait_group %0;\n" :: "n"(GSTAGES - 2) : "memory");
        __syncthreads();
        uint32_t sA = smem_u32(smem + (size_t)(kt & (GSTAGES - 1)) * GSTAGE_BYTES);
        uint32_t sB = sA + GBM * GPITCH * 2;

        #pragma unroll
        for (int ks = 0; ks < 2; ++ks) {
            uint32_t af[4][4];
            uint32_t bf[4][2];
            #pragma unroll
            for (int mt = 0; mt < 4; ++mt) {
                uint32_t addr = sA + 2u * ((wm0 + mt * 16 + a_row) * GPITCH + ks * 16 + a_col);
                ldsm4(af[mt][0], af[mt][1], af[mt][2], af[mt][3], addr);
            }
            #pragma unroll
            for (int nt = 0; nt < 4; ++nt) {
                uint32_t addr = sB + 2u * ((wn0 + nt * 8 + b_row) * GPITCH + ks * 16 + b_col);
                ldsm2(bf[nt][0], bf[nt][1], addr);
            }
            #pragma unroll
            for (int mt = 0; mt < 4; ++mt)
                #pragma unroll
                for (int nt = 0; nt < 4; ++nt)
                    mma_bf16(acc[mt][nt], af[mt], bf[nt]);
        }
        __syncthreads();
        if (kt + GSTAGES - 1 < NK) issue(kt + GSTAGES - 1);
        asm volatile("cp.async.commit_group;\n" ::: "memory");
    }

    // epilogue
    const int er = lane >> 2;
    const int ec = (lane & 3) << 1;
    #pragma unroll
    for (int mt = 0; mt < 4; ++mt) {
        #pragma unroll
        for (int nt = 0; nt < 4; ++nt) {
            const int n0 = bn + wn0 + nt * 8 + ec;
            const float bv0 = __ldg(&bias[n0]);
            const float bv1 = __ldg(&bias[n0 + 1]);
            #pragma unroll
            for (int i = 0; i < 2; ++i) {
                const int m = bm + wm0 + mt * 16 + er + i * 8;
                const float v0 = acc[mt][nt][i * 2 + 0] + bv0;
                const float v1 = acc[mt][nt][i * 2 + 1] + bv1;
                if (MODE == 0) {
                    *(__nv_bfloat162*)(g_h + (size_t)m * CA_ + n0) = __floats2bfloat162_rn(v0, v1);
                } else {
                    const int bt = m / P_;
                    const size_t off = (size_t)(m + bt + 1) * C_ + n0;
                    float2 xr = *(const float2*)(xres + off);
                    float2 o;
                    o.x = xr.x + v0;
                    o.y = xr.y + v1;
                    *(float2*)(outf + off) = o;
                }
            }
        }
    }
}

// ---------------- depthwise 3x3x3 conv ----------------
__global__ __launch_bounds__(CA_)
void conv_kernel(const float* __restrict__ cw, const float* __restrict__ cb) {
    const int ca = threadIdx.x;       // 0..383
    const int bt = blockIdx.x;        // 0..255
    const int y  = blockIdx.y;        // 0..13
    const int t  = bt & 7;

    float w[27];
    #pragma unroll
    for (int j = 0; j < 27; ++j) w[j] = __ldg(&cw[ca * 27 + j]);
    const float bias = __ldg(&cb[ca]);

    for (int x = 0; x < W_; ++x) {
        float acc = bias;
        #pragma unroll
        for (int dt = -1; dt <= 1; ++dt) {
            const int t2 = t + dt;
            if (t2 < 0 || t2 > 7) continue;
            #pragma unroll
            for (int dy = -1; dy <= 1; ++dy) {
                const int y2 = y + dy;
                if (y2 < 0 || y2 > 13) continue;
                #pragma unroll
                for (int dx = -1; dx <= 1; ++dx) {
                    const int x2 = x + dx;
                    if (x2 < 0 || x2 > 13) continue;
                    const size_t idx = ((size_t)((bt + dt) * P_ + y2 * W_ + x2)) * CA_ + ca;
                    acc += w[(dt + 1) * 9 + (dy + 1) * 3 + (dx + 1)] *
                           __bfloat162float(g_h[idx]);
                }
            }
        }
        g_g[((size_t)(bt * P_ + y * W_ + x)) * CA_ + ca] = __float2bfloat16(acc);
    }
}

// ---------------- launch ----------------
extern "C" void kernel_launch(void* const* d_in, const int* in_sizes, int n_in,
                              void* d_out, int out_size) {
    const float* x      = (const float*)d_in[0];
    const float* W1     = (const float*)d_in[1];
    const float* b1     = (const float*)d_in[2];
    const float* conv_w = (const float*)d_in[3];
    const float* conv_b = (const float*)d_in[4];
    const float* W2     = (const float*)d_in[5];
    const float* b2     = (const float*)d_in[6];
    float* out = (float*)d_out;
    (void)in_sizes; (void)n_in; (void)out_size;

    const int smem_bytes = GSTAGES * GSTAGE_BYTES;  // 81920
    cudaFuncSetAttribute(gemm_k<0>, cudaFuncAttributeMaxDynamicSharedMemorySize, smem_bytes);
    cudaFuncSetAttribute(gemm_k<1>, cudaFuncAttributeMaxDynamicSharedMemorySize, smem_bytes);

    prep_weights<<<(CA_ * C_) / 256, 256>>>(W1, W2);
    prep_x<<<(int)(((size_t)M_ * C_ / 4 + 255) / 256), 256>>>((const float4*)x);
    cls_copy<<<(BT_ * C_ / 4) / 256, 256>>>((const float4*)x, (float4*)out);

    gemm_k<0><<<dim3(CA_ / GBN, M_ / GBM), 256, smem_bytes>>>(b1, nullptr, nullptr);

    conv_kernel<<<dim3(BT_, H_), CA_>>>(conv_w, conv_b);

    gemm_k<1><<<dim3(C_ / GBN, M_ / GBM), 256, smem_bytes>>>(b2, x, out);
}

// round 2
// speedup vs baseline: 1.3423x; 1.3423x over previous
#include <cuda_runtime.h>
#include <cuda_bf16.h>
#include <cstdint>

#define B_   32
#define T_   8
#define BT_  256
#define H_   14
#define W_   14
#define P_   196
#define L_   197
#define C_   768
#define CA_  384
#define M_   (BT_*P_)   // 50176

// ---- scratch (static __device__ arrays: allocation-free) ----
__device__ __nv_bfloat16 g_Abf[(size_t)M_ * C_];   // x tokens, bf16   (77 MB)
__device__ __nv_bfloat16 g_W1b[CA_ * C_];          // W1 bf16
__device__ __nv_bfloat16 g_W2b[C_ * CA_];          // W2 bf16
__device__ __nv_bfloat16 g_h[(size_t)M_ * CA_];    // fc1 out          (38.5 MB)
__device__ __nv_bfloat16 g_g[(size_t)M_ * CA_];    // conv out         (38.5 MB)

// ---------------- helpers ----------------
__device__ __forceinline__ uint32_t smem_u32(const void* p) {
    return (uint32_t)__cvta_generic_to_shared(p);
}

__device__ __forceinline__ void cp16(void* sdst, const void* gsrc) {
    uint32_t d = smem_u32(sdst);
    asm volatile("cp.async.cg.shared.global [%0], [%1], 16;\n" :: "r"(d), "l"(gsrc));
}

__device__ __forceinline__ void ldsm4(uint32_t& r0, uint32_t& r1, uint32_t& r2, uint32_t& r3, uint32_t addr) {
    asm volatile("ldmatrix.sync.aligned.m8n8.x4.shared.b16 {%0,%1,%2,%3}, [%4];\n"
                 : "=r"(r0), "=r"(r1), "=r"(r2), "=r"(r3) : "r"(addr));
}

__device__ __forceinline__ void mma_bf16(float (&d)[4], const uint32_t (&a)[4], const uint32_t (&b)[2]) {
    asm volatile(
        "mma.sync.aligned.m16n8k16.row.col.f32.bf16.bf16.f32 "
        "{%0,%1,%2,%3}, {%4,%5,%6,%7}, {%8,%9}, {%0,%1,%2,%3};\n"
        : "+f"(d[0]), "+f"(d[1]), "+f"(d[2]), "+f"(d[3])
        : "r"(a[0]), "r"(a[1]), "r"(a[2]), "r"(a[3]), "r"(b[0]), "r"(b[1]));
}

// ---------------- prep kernels ----------------
__global__ void prep_weights(const float* __restrict__ W1, const float* __restrict__ W2) {
    int i = blockIdx.x * 256 + threadIdx.x;   // grid covers exactly CA_*C_ = 294912
    g_W1b[i] = __float2bfloat16(W1[i]);
    g_W2b[i] = __float2bfloat16(W2[i]);
}

// gather non-CLS tokens of x -> dense bf16 A [M_, C_]
__global__ void prep_x(const float4* __restrict__ x4) {
    size_t i = (size_t)blockIdx.x * 256 + threadIdx.x;   // < M_*C_/4 = 9,633,792
    if (i >= (size_t)M_ * C_ / 4) return;
    size_t e = i * 4;
    int m = (int)(e / C_);
    int k = (int)(e - (size_t)m * C_);
    int bt = m / P_;
    size_t src = ((size_t)(m + bt + 1) * C_ + k) >> 2;
    float4 v = __ldg(&x4[src]);
    __nv_bfloat162* dst = (__nv_bfloat162*)(g_Abf + e);
    dst[0] = __floats2bfloat162_rn(v.x, v.y);
    dst[1] = __floats2bfloat162_rn(v.z, v.w);
}

__global__ void cls_copy(const float4* __restrict__ x4, float4* __restrict__ o4) {
    int i = blockIdx.x * 256 + threadIdx.x;  // grid covers exactly BT_*C_/4 = 49152
    int bt = i / (C_ / 4);
    int j = i - bt * (C_ / 4);
    size_t off = (size_t)bt * L_ * (C_ / 4) + j;
    o4[off] = x4[off];
}

// ---------------- GEMM (bf16 mma.sync, cp.async 4-stage) ----------------
#define GBM 128
#define GBN 128
#define GBK 32
#define GSTAGES 4
#define GPITCH 40            // bf16 elems per smem row (32 + 8 pad)
#define GSTAGE_BYTES (2 * GBM * GPITCH * 2)   // A tile + B tile = 20480

template <int MODE>
__global__ __launch_bounds__(256)
void gemm_k(const float* __restrict__ bias,
            const float* __restrict__ xres,
            float* __restrict__ outf) {
    constexpr int KD = (MODE == 0) ? C_ : CA_;
    constexpr int NK = KD / GBK;
    const __nv_bfloat16* __restrict__ A  = (MODE == 0) ? g_Abf : g_g;
    const __nv_bfloat16* __restrict__ Bw = (MODE == 0) ? g_W1b : g_W2b;

    extern __shared__ char smem[];
    const int tid  = threadIdx.x;
    const int lane = tid & 31;
    const int warp = tid >> 5;
    const int bm = blockIdx.y * GBM;
    const int bn = blockIdx.x * GBN;
    const int wm0 = (warp >> 2) * 64;
    const int wn0 = (warp & 3) * 32;

    const int rA0 = tid >> 2, cA0 = tid & 3;
    const int rA1 = (tid + 256) >> 2, cA1 = (tid + 256) & 3;

    auto issue = [&](int kt) {
        const int k0 = kt * GBK;
        char* st = smem + (size_t)(kt & (GSTAGES - 1)) * GSTAGE_BYTES;
        cp16(st + rA0 * 80 + cA0 * 16, A + (size_t)(bm + rA0) * KD + k0 + cA0 * 8);
        cp16(st + rA1 * 80 + cA1 * 16, A + (size_t)(bm + rA1) * KD + k0 + cA1 * 8);
        char* stB = st + GBM * GPITCH * 2;
        cp16(stB + rA0 * 80 + cA0 * 16, Bw + (size_t)(bn + rA0) * KD + k0 + cA0 * 8);
        cp16(stB + rA1 * 80 + cA1 * 16, Bw + (size_t)(bn + rA1) * KD + k0 + cA1 * 8);
    };

    #pragma unroll
    for (int s = 0; s < GSTAGES - 1; ++s) {
        issue(s);
        asm volatile("cp.async.commit_group;\n" ::: "memory");
    }

    float acc[4][4][4];
    #pragma unroll
    for (int mt = 0; mt < 4; ++mt)
        #pragma unroll
        for (int nt = 0; nt < 4; ++nt)
            #pragma unroll
            for (int i = 0; i < 4; ++i) acc[mt][nt][i] = 0.0f;

    const int a_row = lane & 15;
    const int a_col = (lane >> 4) << 3;
    // B ldsm4: two n-tiles per instruction. matrix index g = lane>>3:
    //   row = (pair*2 + (g>>1))*8 + (lane&7), col = ks*16 + (g&1)*8
    const int b_row = lane & 7;
    const int b_sub = (lane >> 4);          // which n-tile of the pair
    const int b_col = ((lane >> 3) & 1) << 3;

    for (int kt = 0; kt < NK; ++kt) {
        asm volatile("cp.async.wait_group %0;\n" :: "n"(GSTAGES - 2) : "memory");
        __syncthreads();
        uint32_t sA = smem_u32(smem + (size_t)(kt & (GSTAGES - 1)) * GSTAGE_BYTES);
        uint32_t sB = sA + GBM * GPITCH * 2;

        #pragma unroll
        for (int ks = 0; ks < 2; ++ks) {
            uint32_t af[4][4];
            uint32_t bf[4][2];
            #pragma unroll
            for (int mt = 0; mt < 4; ++mt) {
                uint32_t addr = sA + 2u * ((wm0 + mt * 16 + a_row) * GPITCH + ks * 16 + a_col);
                ldsm4(af[mt][0], af[mt][1], af[mt][2], af[mt][3], addr);
            }
            #pragma unroll
            for (int p = 0; p < 2; ++p) {
                uint32_t addr = sB + 2u * ((wn0 + (p * 2 + b_sub) * 8 + b_row) * GPITCH + ks * 16 + b_col);
                ldsm4(bf[p * 2][0], bf[p * 2][1], bf[p * 2 + 1][0], bf[p * 2 + 1][1], addr);
            }
            #pragma unroll
            for (int mt = 0; mt < 4; ++mt)
                #pragma unroll
                for (int nt = 0; nt < 4; ++nt)
                    mma_bf16(acc[mt][nt], af[mt], bf[nt]);
        }
        __syncthreads();
        if (kt + GSTAGES - 1 < NK) issue(kt + GSTAGES - 1);
        asm volatile("cp.async.commit_group;\n" ::: "memory");
    }

    // epilogue
    const int er = lane >> 2;
    const int ec = (lane & 3) << 1;
    #pragma unroll
    for (int mt = 0; mt < 4; ++mt) {
        #pragma unroll
        for (int nt = 0; nt < 4; ++nt) {
            const int n0 = bn + wn0 + nt * 8 + ec;
            const float bv0 = __ldg(&bias[n0]);
            const float bv1 = __ldg(&bias[n0 + 1]);
            #pragma unroll
            for (int i = 0; i < 2; ++i) {
                const int m = bm + wm0 + mt * 16 + er + i * 8;
                const float v0 = acc[mt][nt][i * 2 + 0] + bv0;
                const float v1 = acc[mt][nt][i * 2 + 1] + bv1;
                if (MODE == 0) {
                    *(__nv_bfloat162*)(g_h + (size_t)m * CA_ + n0) = __floats2bfloat162_rn(v0, v1);
                } else {
                    const int bt = m / P_;
                    const size_t off = (size_t)(m + bt + 1) * C_ + n0;
                    float2 xr = *(const float2*)(xres + off);
                    float2 o;
                    o.x = xr.x + v0;
                    o.y = xr.y + v1;
                    *(float2*)(outf + off) = o;
                }
            }
        }
    }
}

// ---------------- depthwise 3x3x3 conv (vectorized, sliding-x window) ----------------
// block: 192 threads = 192 bf162 channel pairs (384 ch). grid (BT_, H_).
// 9 (dt,dy) lines with precomputed validity; 9 bf162 loads per output x.
__global__ __launch_bounds__(192)
void conv_kernel(const float* __restrict__ cw, const float* __restrict__ cb) {
    const int cp = threadIdx.x;       // channel pair 0..191
    const int bt = blockIdx.x;        // 0..255
    const int y  = blockIdx.y;        // 0..13
    const int t  = bt & 7;
    const int c0 = cp * 2;

    // per-channel-pair weights: wv[3*j + (dx+1)] with j=(dt+1)*3+(dy+1)
    float2 wv[27];
    #pragma unroll
    for (int j = 0; j < 27; ++j) {
        wv[j].x = __ldg(&cw[c0 * 27 + j]);
        wv[j].y = __ldg(&cw[(c0 + 1) * 27 + j]);
    }
    const float bx = __ldg(&cb[c0]);
    const float by = __ldg(&cb[c0 + 1]);

    const uint32_t* lp[9];
    bool lv[9];
    #pragma unroll
    for (int dt = -1; dt <= 1; ++dt) {
        #pragma unroll
        for (int dy = -1; dy <= 1; ++dy) {
            const int j = (dt + 1) * 3 + (dy + 1);
            const int t2 = t + dt;
            const int y2 = y + dy;
            lv[j] = ((unsigned)t2 < (unsigned)T_) && ((unsigned)y2 < (unsigned)H_);
            const int bt2 = lv[j] ? (bt + dt) : bt;
            const int yy  = lv[j] ? y2 : y;
            lp[j] = (const uint32_t*)(g_h + (size_t)(bt2 * P_ + yy * W_) * CA_) + cp;
        }
    }

    uint32_t v0[9], v1[9], v2[9];
    #pragma unroll
    for (int j = 0; j < 9; ++j) {
        v0[j] = 0u;
        v1[j] = lv[j] ? __ldg(lp[j]) : 0u;   // x = 0 (x stride = CA_/2 = 192 words)
    }

    uint32_t* gout = (uint32_t*)(g_g + (size_t)(bt * P_ + y * W_) * CA_) + cp;

    for (int x = 0; x < W_; ++x) {
        const bool in = (x + 1) < W_;
        #pragma unroll
        for (int j = 0; j < 9; ++j)
            v2[j] = (lv[j] && in) ? __ldg(lp[j] + (size_t)(x + 1) * (CA_ / 2)) : 0u;

        float ax = bx, ay = by;
        #pragma unroll
        for (int j = 0; j < 9; ++j) {
            const float2 f0 = __bfloat1622float2(*(const __nv_bfloat162*)&v0[j]);
            const float2 f1 = __bfloat1622float2(*(const __nv_bfloat162*)&v1[j]);
            const float2 f2 = __bfloat1622float2(*(const __nv_bfloat162*)&v2[j]);
            ax = fmaf(wv[3 * j + 0].x, f0.x, ax);
            ay = fmaf(wv[3 * j + 0].y, f0.y, ay);
            ax = fmaf(wv[3 * j + 1].x, f1.x, ax);
            ay = fmaf(wv[3 * j + 1].y, f1.y, ay);
            ax = fmaf(wv[3 * j + 2].x, f2.x, ax);
            ay = fmaf(wv[3 * j + 2].y, f2.y, ay);
        }
        const __nv_bfloat162 r = __floats2bfloat162_rn(ax, ay);
        gout[(size_t)x * (CA_ / 2)] = *(const uint32_t*)&r;

        #pragma unroll
        for (int j = 0; j < 9; ++j) { v0[j] = v1[j]; v1[j] = v2[j]; }
    }
}

// ---------------- launch ----------------
extern "C" void kernel_launch(void* const* d_in, const int* in_sizes, int n_in,
                              void* d_out, int out_size) {
    const float* x      = (const float*)d_in[0];
    const float* W1     = (const float*)d_in[1];
    const float* b1     = (const float*)d_in[2];
    const float* conv_w = (const float*)d_in[3];
    const float* conv_b = (const float*)d_in[4];
    const float* W2     = (const float*)d_in[5];
    const float* b2     = (const float*)d_in[6];
    float* out = (float*)d_out;
    (void)in_sizes; (void)n_in; (void)out_size;

    const int smem_bytes = GSTAGES * GSTAGE_BYTES;  // 81920
    cudaFuncSetAttribute(gemm_k<0>, cudaFuncAttributeMaxDynamicSharedMemorySize, smem_bytes);
    cudaFuncSetAttribute(gemm_k<1>, cudaFuncAttributeMaxDynamicSharedMemorySize, smem_bytes);

    prep_weights<<<(CA_ * C_) / 256, 256>>>(W1, W2);
    prep_x<<<(int)(((size_t)M_ * C_ / 4 + 255) / 256), 256>>>((const float4*)x);
    cls_copy<<<(BT_ * C_ / 4) / 256, 256>>>((const float4*)x, (float4*)out);

    gemm_k<0><<<dim3(CA_ / GBN, M_ / GBM), 256, smem_bytes>>>(b1, nullptr, nullptr);

    conv_kernel<<<dim3(BT_, H_), 192>>>(conv_w, conv_b);

    gemm_k<1><<<dim3(C_ / GBN, M_ / GBM), 256, smem_bytes>>>(b2, x, out);
}

// round 4
// speedup vs baseline: 1.5225x; 1.1343x over previous
#include <cuda_runtime.h>
#include <cuda_bf16.h>
#include <cstdint>

#define B_   32
#define T_   8
#define BT_  256
#define H_   14
#define W_   14
#define P_   196
#define L_   197
#define C_   768
#define CA_  384
#define M_   (BT_*P_)   // 50176

// ---- scratch (static __device__ arrays: allocation-free) ----
__device__ __nv_bfloat16 g_Abf[(size_t)M_ * C_];   // x tokens, bf16   (77 MB)
__device__ __nv_bfloat16 g_W1b[CA_ * C_];          // W1 bf16
__device__ __nv_bfloat16 g_W2b[C_ * CA_];          // W2 bf16
__device__ __nv_bfloat16 g_h[(size_t)M_ * CA_];    // fc1 out          (38.5 MB)
__device__ __nv_bfloat16 g_g[(size_t)M_ * CA_];    // conv out         (38.5 MB)

// ---------------- helpers ----------------
__device__ __forceinline__ uint32_t smem_u32(const void* p) {
    return (uint32_t)__cvta_generic_to_shared(p);
}

__device__ __forceinline__ void cp16(void* sdst, const void* gsrc) {
    uint32_t d = smem_u32(sdst);
    asm volatile("cp.async.cg.shared.global [%0], [%1], 16;\n" :: "r"(d), "l"(gsrc));
}

__device__ __forceinline__ void ldsm4(uint32_t& r0, uint32_t& r1, uint32_t& r2, uint32_t& r3, uint32_t addr) {
    asm volatile("ldmatrix.sync.aligned.m8n8.x4.shared.b16 {%0,%1,%2,%3}, [%4];\n"
                 : "=r"(r0), "=r"(r1), "=r"(r2), "=r"(r3) : "r"(addr));
}

__device__ __forceinline__ void mma_bf16(float (&d)[4], const uint32_t (&a)[4], const uint32_t (&b)[2]) {
    asm volatile(
        "mma.sync.aligned.m16n8k16.row.col.f32.bf16.bf16.f32 "
        "{%0,%1,%2,%3}, {%4,%5,%6,%7}, {%8,%9}, {%0,%1,%2,%3};\n"
        : "+f"(d[0]), "+f"(d[1]), "+f"(d[2]), "+f"(d[3])
        : "r"(a[0]), "r"(a[1]), "r"(a[2]), "r"(a[3]), "r"(b[0]), "r"(b[1]));
}

// ---------------- prep kernels ----------------
__global__ void prep_weights(const float* __restrict__ W1, const float* __restrict__ W2) {
    int i = blockIdx.x * 256 + threadIdx.x;
    g_W1b[i] = __float2bfloat16(W1[i]);
    g_W2b[i] = __float2bfloat16(W2[i]);
}

// gather non-CLS tokens of x -> dense bf16 A [M_, C_]
__global__ void prep_x(const float4* __restrict__ x4) {
    size_t i = (size_t)blockIdx.x * 256 + threadIdx.x;
    if (i >= (size_t)M_ * C_ / 4) return;
    size_t e = i * 4;
    int m = (int)(e / C_);
    int k = (int)(e - (size_t)m * C_);
    int bt = m / P_;
    size_t src = ((size_t)(m + bt + 1) * C_ + k) >> 2;
    float4 v = __ldg(&x4[src]);
    __nv_bfloat162* dst = (__nv_bfloat162*)(g_Abf + e);
    dst[0] = __floats2bfloat162_rn(v.x, v.y);
    dst[1] = __floats2bfloat162_rn(v.z, v.w);
}

__global__ void cls_copy(const float4* __restrict__ x4, float4* __restrict__ o4) {
    int i = blockIdx.x * 256 + threadIdx.x;
    int bt = i / (C_ / 4);
    int j = i - bt * (C_ / 4);
    size_t off = (size_t)bt * L_ * (C_ / 4) + j;
    o4[off] = x4[off];
}

// ---------------- GEMM (bf16 mma.sync, cp.async 4-stage, frag-pipelined) ----------------
#define GBM 128
#define GBN 128
#define GBK 32
#define GSTAGES 4
#define GPITCH 40            // bf16 elems per smem row (32 + 8 pad)
#define GSTAGE_BYTES (2 * GBM * GPITCH * 2)   // A tile + B tile = 20480

template <int MODE>
__global__ __launch_bounds__(256, 2)
void gemm_k(const float* __restrict__ bias,
            const float* __restrict__ xres,
            float* __restrict__ outf) {
    constexpr int KD = (MODE == 0) ? C_ : CA_;
    constexpr int NK = KD / GBK;
    const __nv_bfloat16* __restrict__ A  = (MODE == 0) ? g_Abf : g_g;
    const __nv_bfloat16* __restrict__ Bw = (MODE == 0) ? g_W1b : g_W2b;

    extern __shared__ char smem[];
    const int tid  = threadIdx.x;
    const int lane = tid & 31;
    const int warp = tid >> 5;
    const int bm = blockIdx.y * GBM;
    const int bn = blockIdx.x * GBN;
    const int wm0 = (warp >> 2) * 64;
    const int wn0 = (warp & 3) * 32;

    const int rA0 = tid >> 2, cA0 = tid & 3;   // second slot is rA0+64, same col

    auto issue = [&](int kt) {
        const int k0 = kt * GBK;
        char* st = smem + (size_t)(kt & (GSTAGES - 1)) * GSTAGE_BYTES;
        const __nv_bfloat16* gA = A + (size_t)(bm + rA0) * KD + k0 + cA0 * 8;
        cp16(st + rA0 * 80 + cA0 * 16, gA);
        cp16(st + (rA0 + 64) * 80 + cA0 * 16, gA + (size_t)64 * KD);
        char* stB = st + GBM * GPITCH * 2;
        const __nv_bfloat16* gB = Bw + (size_t)(bn + rA0) * KD + k0 + cA0 * 8;
        cp16(stB + rA0 * 80 + cA0 * 16, gB);
        cp16(stB + (rA0 + 64) * 80 + cA0 * 16, gB + (size_t)64 * KD);
    };

    #pragma unroll
    for (int s = 0; s < GSTAGES - 1; ++s) {
        issue(s);
        asm volatile("cp.async.commit_group;\n" ::: "memory");
    }

    float acc[4][4][4];
    #pragma unroll
    for (int mt = 0; mt < 4; ++mt)
        #pragma unroll
        for (int nt = 0; nt < 4; ++nt)
            #pragma unroll
            for (int i = 0; i < 4; ++i) acc[mt][nt][i] = 0.0f;

    const int a_row = lane & 15;
    const int a_col = (lane >> 4) << 3;
    const int b_row = lane & 7;
    const int b_sub = (lane >> 4);
    const int b_col = ((lane >> 3) & 1) << 3;

    uint32_t af[2][4][4];
    uint32_t bf[2][4][2];

    auto load_frags = [&](int kt, int ks, int buf) {
        uint32_t sA = smem_u32(smem + (size_t)(kt & (GSTAGES - 1)) * GSTAGE_BYTES);
        uint32_t sB = sA + GBM * GPITCH * 2;
        #pragma unroll
        for (int mt = 0; mt < 4; ++mt) {
            uint32_t addr = sA + 2u * ((wm0 + mt * 16 + a_row) * GPITCH + ks * 16 + a_col);
            ldsm4(af[buf][mt][0], af[buf][mt][1], af[buf][mt][2], af[buf][mt][3], addr);
        }
        #pragma unroll
        for (int p = 0; p < 2; ++p) {
            uint32_t addr = sB + 2u * ((wn0 + (p * 2 + b_sub) * 8 + b_row) * GPITCH + ks * 16 + b_col);
            ldsm4(bf[buf][p * 2][0], bf[buf][p * 2][1], bf[buf][p * 2 + 1][0], bf[buf][p * 2 + 1][1], addr);
        }
    };

    asm volatile("cp.async.wait_group %0;\n" :: "n"(GSTAGES - 2) : "memory");
    __syncthreads();
    load_frags(0, 0, 0);

    for (int kt = 0; kt < NK; ++kt) {
        // prefetch second k-slice of this tile
        load_frags(kt, 1, 1);
        if (kt + GSTAGES - 1 < NK) issue(kt + GSTAGES - 1);
        asm volatile("cp.async.commit_group;\n" ::: "memory");

        #pragma unroll
        for (int mt = 0; mt < 4; ++mt)
            #pragma unroll
            for (int nt = 0; nt < 4; ++nt)
                mma_bf16(acc[mt][nt], af[0][mt], bf[0][nt]);

        // after this wait+sync, tile kt+1 is complete and visible block-wide
        asm volatile("cp.async.wait_group %0;\n" :: "n"(GSTAGES - 2) : "memory");
        __syncthreads();
        if (kt + 1 < NK) load_frags(kt + 1, 0, 0);

        #pragma unroll
        for (int mt = 0; mt < 4; ++mt)
            #pragma unroll
            for (int nt = 0; nt < 4; ++nt)
                mma_bf16(acc[mt][nt], af[1][mt], bf[1][nt]);
    }

    // epilogue
    const int er = lane >> 2;
    const int ec = (lane & 3) << 1;
    #pragma unroll
    for (int mt = 0; mt < 4; ++mt) {
        #pragma unroll
        for (int nt = 0; nt < 4; ++nt) {
            const int n0 = bn + wn0 + nt * 8 + ec;
            const float bv0 = __ldg(&bias[n0]);
            const float bv1 = __ldg(&bias[n0 + 1]);
            #pragma unroll
            for (int i = 0; i < 2; ++i) {
                const int m = bm + wm0 + mt * 16 + er + i * 8;
                const float v0 = acc[mt][nt][i * 2 + 0] + bv0;
                const float v1 = acc[mt][nt][i * 2 + 1] + bv1;
                if (MODE == 0) {
                    *(__nv_bfloat162*)(g_h + (size_t)m * CA_ + n0) = __floats2bfloat162_rn(v0, v1);
                } else {
                    const int bt = m / P_;
                    const size_t off = (size_t)(m + bt + 1) * C_ + n0;
                    float2 xr = *(const float2*)(xres + off);
                    float2 o;
                    o.x = xr.x + v0;
                    o.y = xr.y + v1;
                    *(float2*)(outf + off) = o;
                }
            }
        }
    }
}

// ---------------- depthwise 3x3x3 conv (vectorized, sliding-x window) ----------------
__global__ __launch_bounds__(192)
void conv_kernel(const float* __restrict__ cw, const float* __restrict__ cb) {
    const int cp = threadIdx.x;       // channel pair 0..191
    const int bt = blockIdx.x;        // 0..255
    const int y  = blockIdx.y;        // 0..13
    const int t  = bt & 7;
    const int c0 = cp * 2;

    float2 wv[27];
    #pragma unroll
    for (int j = 0; j < 27; ++j) {
        wv[j].x = __ldg(&cw[c0 * 27 + j]);
        wv[j].y = __ldg(&cw[(c0 + 1) * 27 + j]);
    }
    const float bx = __ldg(&cb[c0]);
    const float by = __ldg(&cb[c0 + 1]);

    const uint32_t* lp[9];
    bool lv[9];
    #pragma unroll
    for (int dt = -1; dt <= 1; ++dt) {
        #pragma unroll
        for (int dy = -1; dy <= 1; ++dy) {
            const int j = (dt + 1) * 3 + (dy + 1);
            const int t2 = t + dt;
            const int y2 = y + dy;
            lv[j] = ((unsigned)t2 < (unsigned)T_) && ((unsigned)y2 < (unsigned)H_);
            const int bt2 = lv[j] ? (bt + dt) : bt;
            const int yy  = lv[j] ? y2 : y;
            lp[j] = (const uint32_t*)(g_h + (size_t)(bt2 * P_ + yy * W_) * CA_) + cp;
        }
    }

    uint32_t v0[9], v1[9], v2[9];
    #pragma unroll
    for (int j = 0; j < 9; ++j) {
        v0[j] = 0u;
        v1[j] = lv[j] ? __ldg(lp[j]) : 0u;
    }

    uint32_t* gout = (uint32_t*)(g_g + (size_t)(bt * P_ + y * W_) * CA_) + cp;

    for (int x = 0; x < W_; ++x) {
        const bool in = (x + 1) < W_;
        #pragma unroll
        for (int j = 0; j < 9; ++j)
            v2[j] = (lv[j] && in) ? __ldg(lp[j] + (size_t)(x + 1) * (CA_ / 2)) : 0u;

        float ax = bx, ay = by;
        #pragma unroll
        for (int j = 0; j < 9; ++j) {
            const float2 f0 = __bfloat1622float2(*(const __nv_bfloat162*)&v0[j]);
            const float2 f1 = __bfloat1622float2(*(const __nv_bfloat162*)&v1[j]);
            const float2 f2 = __bfloat1622float2(*(const __nv_bfloat162*)&v2[j]);
            ax = fmaf(wv[3 * j + 0].x, f0.x, ax);
            ay = fmaf(wv[3 * j + 0].y, f0.y, ay);
            ax = fmaf(wv[3 * j + 1].x, f1.x, ax);
            ay = fmaf(wv[3 * j + 1].y, f1.y, ay);
            ax = fmaf(wv[3 * j + 2].x, f2.x, ax);
            ay = fmaf(wv[3 * j + 2].y, f2.y, ay);
        }
        const __nv_bfloat162 r = __floats2bfloat162_rn(ax, ay);
        gout[(size_t)x * (CA_ / 2)] = *(const uint32_t*)&r;

        #pragma unroll
        for (int j = 0; j < 9; ++j) { v0[j] = v1[j]; v1[j] = v2[j]; }
    }
}

// ---------------- launch ----------------
extern "C" void kernel_launch(void* const* d_in, const int* in_sizes, int n_in,
                              void* d_out, int out_size) {
    const float* x      = (const float*)d_in[0];
    const float* W1     = (const float*)d_in[1];
    const float* b1     = (const float*)d_in[2];
    const float* conv_w = (const float*)d_in[3];
    const float* conv_b = (const float*)d_in[4];
    const float* W2     = (const float*)d_in[5];
    const float* b2     = (const float*)d_in[6];
    float* out = (float*)d_out;
    (void)in_sizes; (void)n_in; (void)out_size;

    const int smem_bytes = GSTAGES * GSTAGE_BYTES;  // 81920
    cudaFuncSetAttribute(gemm_k<0>, cudaFuncAttributeMaxDynamicSharedMemorySize, smem_bytes);
    cudaFuncSetAttribute(gemm_k<1>, cudaFuncAttributeMaxDynamicSharedMemorySize, smem_bytes);

    prep_weights<<<(CA_ * C_) / 256, 256>>>(W1, W2);
    prep_x<<<(int)(((size_t)M_ * C_ / 4 + 255) / 256), 256>>>((const float4*)x);
    cls_copy<<<(BT_ * C_ / 4) / 256, 256>>>((const float4*)x, (float4*)out);

    gemm_k<0><<<dim3(CA_ / GBN, M_ / GBM), 256, smem_bytes>>>(b1, nullptr, nullptr);

    conv_kernel<<<dim3(BT_, H_), 192>>>(conv_w, conv_b);

    gemm_k<1><<<dim3(C_ / GBN, M_ / GBM), 256, smem_bytes>>>(b2, x, out);
}

// round 6
// speedup vs baseline: 1.5715x; 1.0322x over previous
#include <cuda_runtime.h>
#include <cuda_bf16.h>
#include <cstdint>

#define B_   32
#define T_   8
#define BT_  256
#define H_   14
#define W_   14
#define P_   196
#define L_   197
#define C_   768
#define CA_  384
#define M_   (BT_*P_)   // 50176

// ---- scratch (static __device__ arrays: allocation-free) ----
__device__ __nv_bfloat16 g_Abf[(size_t)M_ * C_];   // x tokens, bf16   (77 MB)
__device__ __nv_bfloat16 g_W1b[CA_ * C_];          // W1 bf16
__device__ __nv_bfloat16 g_W2b[C_ * CA_];          // W2 bf16
__device__ __nv_bfloat16 g_h[(size_t)M_ * CA_];    // fc1 out          (38.5 MB)
__device__ __nv_bfloat16 g_g[(size_t)M_ * CA_];    // conv out         (38.5 MB)

// ---------------- helpers ----------------
__device__ __forceinline__ uint32_t smem_u32(const void* p) {
    return (uint32_t)__cvta_generic_to_shared(p);
}

__device__ __forceinline__ void cp16(void* sdst, const void* gsrc) {
    uint32_t d = smem_u32(sdst);
    asm volatile("cp.async.cg.shared.global [%0], [%1], 16;\n" :: "r"(d), "l"(gsrc));
}

__device__ __forceinline__ void ldsm4(uint32_t& r0, uint32_t& r1, uint32_t& r2, uint32_t& r3, uint32_t addr) {
    asm volatile("ldmatrix.sync.aligned.m8n8.x4.shared.b16 {%0,%1,%2,%3}, [%4];\n"
                 : "=r"(r0), "=r"(r1), "=r"(r2), "=r"(r3) : "r"(addr));
}

__device__ __forceinline__ void mma_bf16(float (&d)[4], const uint32_t (&a)[4], const uint32_t (&b)[2]) {
    asm volatile(
        "mma.sync.aligned.m16n8k16.row.col.f32.bf16.bf16.f32 "
        "{%0,%1,%2,%3}, {%4,%5,%6,%7}, {%8,%9}, {%0,%1,%2,%3};\n"
        : "+f"(d[0]), "+f"(d[1]), "+f"(d[2]), "+f"(d[3])
        : "r"(a[0]), "r"(a[1]), "r"(a[2]), "r"(a[3]), "r"(b[0]), "r"(b[1]));
}

// ---------------- prep kernels ----------------
__global__ void prep_weights(const float* __restrict__ W1, const float* __restrict__ W2) {
    int i = blockIdx.x * 256 + threadIdx.x;
    g_W1b[i] = __float2bfloat16(W1[i]);
    g_W2b[i] = __float2bfloat16(W2[i]);
}

// gather non-CLS tokens of x -> dense bf16 A [M_, C_]
__global__ void prep_x(const float4* __restrict__ x4) {
    size_t i = (size_t)blockIdx.x * 256 + threadIdx.x;
    if (i >= (size_t)M_ * C_ / 4) return;
    size_t e = i * 4;
    int m = (int)(e / C_);
    int k = (int)(e - (size_t)m * C_);
    int bt = m / P_;
    size_t src = ((size_t)(m + bt + 1) * C_ + k) >> 2;
    float4 v = __ldg(&x4[src]);
    __nv_bfloat162* dst = (__nv_bfloat162*)(g_Abf + e);
    dst[0] = __floats2bfloat162_rn(v.x, v.y);
    dst[1] = __floats2bfloat162_rn(v.z, v.w);
}

__global__ void cls_copy(const float4* __restrict__ x4, float4* __restrict__ o4) {
    int i = blockIdx.x * 256 + threadIdx.x;
    int bt = i / (C_ / 4);
    int j = i - bt * (C_ / 4);
    size_t off = (size_t)bt * L_ * (C_ / 4) + j;
    o4[off] = x4[off];
}

// ---------------- GEMM (bf16 mma.sync, cp.async 4-stage, frag-pipelined) ----------------
#define GBM 128
#define GBN 128
#define GBK 32
#define GSTAGES 4
#define GPITCH 40            // bf16 elems per smem row (32 + 8 pad)
#define GSTAGE_BYTES (2 * GBM * GPITCH * 2)   // A tile + B tile = 20480

template <int MODE>
__global__ __launch_bounds__(256, 2)
void gemm_k(const float* __restrict__ bias,
            const float* __restrict__ xres,
            float* __restrict__ outf) {
    constexpr int KD = (MODE == 0) ? C_ : CA_;
    constexpr int NK = KD / GBK;
    const __nv_bfloat16* __restrict__ A  = (MODE == 0) ? g_Abf : g_g;
    const __nv_bfloat16* __restrict__ Bw = (MODE == 0) ? g_W1b : g_W2b;

    extern __shared__ char smem[];
    const int tid  = threadIdx.x;
    const int lane = tid & 31;
    const int warp = tid >> 5;
    const int bm = blockIdx.y * GBM;
    const int bn = blockIdx.x * GBN;
    const int wm0 = (warp >> 2) * 64;
    const int wn0 = (warp & 3) * 32;

    const int rA0 = tid >> 2, cA0 = tid & 3;   // second slot is rA0+64, same col

    auto issue = [&](int kt) {
        const int k0 = kt * GBK;
        char* st = smem + (size_t)(kt & (GSTAGES - 1)) * GSTAGE_BYTES;
        const __nv_bfloat16* gA = A + (size_t)(bm + rA0) * KD + k0 + cA0 * 8;
        cp16(st + rA0 * 80 + cA0 * 16, gA);
        cp16(st + (rA0 + 64) * 80 + cA0 * 16, gA + (size_t)64 * KD);
        char* stB = st + GBM * GPITCH * 2;
        const __nv_bfloat16* gB = Bw + (size_t)(bn + rA0) * KD + k0 + cA0 * 8;
        cp16(stB + rA0 * 80 + cA0 * 16, gB);
        cp16(stB + (rA0 + 64) * 80 + cA0 * 16, gB + (size_t)64 * KD);
    };

    #pragma unroll
    for (int s = 0; s < GSTAGES - 1; ++s) {
        issue(s);
        asm volatile("cp.async.commit_group;\n" ::: "memory");
    }

    float acc[4][4][4];
    #pragma unroll
    for (int mt = 0; mt < 4; ++mt)
        #pragma unroll
        for (int nt = 0; nt < 4; ++nt)
            #pragma unroll
            for (int i = 0; i < 4; ++i) acc[mt][nt][i] = 0.0f;

    const int a_row = lane & 15;
    const int a_col = (lane >> 4) << 3;
    const int b_row = lane & 7;
    const int b_sub = (lane >> 4);
    const int b_col = ((lane >> 3) & 1) << 3;

    uint32_t af[2][4][4];
    uint32_t bf[2][4][2];

    auto load_frags = [&](int kt, int ks, int buf) {
        uint32_t sA = smem_u32(smem + (size_t)(kt & (GSTAGES - 1)) * GSTAGE_BYTES);
        uint32_t sB = sA + GBM * GPITCH * 2;
        #pragma unroll
        for (int mt = 0; mt < 4; ++mt) {
            uint32_t addr = sA + 2u * ((wm0 + mt * 16 + a_row) * GPITCH + ks * 16 + a_col);
            ldsm4(af[buf][mt][0], af[buf][mt][1], af[buf][mt][2], af[buf][mt][3], addr);
        }
        #pragma unroll
        for (int p = 0; p < 2; ++p) {
            uint32_t addr = sB + 2u * ((wn0 + (p * 2 + b_sub) * 8 + b_row) * GPITCH + ks * 16 + b_col);
            ldsm4(bf[buf][p * 2][0], bf[buf][p * 2][1], bf[buf][p * 2 + 1][0], bf[buf][p * 2 + 1][1], addr);
        }
    };

    asm volatile("cp.async.wait_group %0;\n" :: "n"(GSTAGES - 2) : "memory");
    __syncthreads();
    load_frags(0, 0, 0);

    for (int kt = 0; kt < NK; ++kt) {
        load_frags(kt, 1, 1);
        if (kt + GSTAGES - 1 < NK) issue(kt + GSTAGES - 1);
        asm volatile("cp.async.commit_group;\n" ::: "memory");

        #pragma unroll
        for (int mt = 0; mt < 4; ++mt)
            #pragma unroll
            for (int nt = 0; nt < 4; ++nt)
                mma_bf16(acc[mt][nt], af[0][mt], bf[0][nt]);

        asm volatile("cp.async.wait_group %0;\n" :: "n"(GSTAGES - 2) : "memory");
        __syncthreads();
        if (kt + 1 < NK) load_frags(kt + 1, 0, 0);

        #pragma unroll
        for (int mt = 0; mt < 4; ++mt)
            #pragma unroll
            for (int nt = 0; nt < 4; ++nt)
                mma_bf16(acc[mt][nt], af[1][mt], bf[1][nt]);
    }

    // epilogue
    const int er = lane >> 2;
    const int ec = (lane & 3) << 1;
    #pragma unroll
    for (int mt = 0; mt < 4; ++mt) {
        #pragma unroll
        for (int nt = 0; nt < 4; ++nt) {
            const int n0 = bn + wn0 + nt * 8 + ec;
            const float bv0 = __ldg(&bias[n0]);
            const float bv1 = __ldg(&bias[n0 + 1]);
            #pragma unroll
            for (int i = 0; i < 2; ++i) {
                const int m = bm + wm0 + mt * 16 + er + i * 8;
                const float v0 = acc[mt][nt][i * 2 + 0] + bv0;
                const float v1 = acc[mt][nt][i * 2 + 1] + bv1;
                if (MODE == 0) {
                    *(__nv_bfloat162*)(g_h + (size_t)m * CA_ + n0) = __floats2bfloat162_rn(v0, v1);
                } else {
                    const int bt = m / P_;
                    const size_t off = (size_t)(m + bt + 1) * C_ + n0;
                    float2 xr = *(const float2*)(xres + off);
                    float2 o;
                    o.x = xr.x + v0;
                    o.y = xr.y + v1;
                    *(float2*)(outf + off) = o;
                }
            }
        }
    }
}

// ---------------- depthwise 3x3x3 conv (smem-tiled, sliding-x window) ----------------
// block: 448 threads = 14 warps. warp = y row (0..13), lane = channel pair (0..31).
// grid: (BT_, CA_/64). Block loads 3 temporal slabs of [196 pos][32 pairs] into smem
// (zero-filled at t edges), stages weights+bias in smem, computes with 9 LDS per x.
#define CONV_THREADS 448
#define SLAB_WORDS   (P_ * 32)            // 6272 uint32 = 25088 B
#define CONV_DATA_B  (3 * SLAB_WORDS * 4) // 75264
#define CONV_W_B     (64 * 27 * 4)        // 6912
#define CONV_SMEM_B  (CONV_DATA_B + CONV_W_B + 64 * 4)

__global__ __launch_bounds__(CONV_THREADS, 1)
void conv_kernel(const float* __restrict__ cw, const float* __restrict__ cb) {
    extern __shared__ char csm[];
    uint32_t* s_data = (uint32_t*)csm;                    // [3][196][32]
    float*    s_w    = (float*)(csm + CONV_DATA_B);       // [64][27]
    float*    s_b    = (float*)(csm + CONV_DATA_B + CONV_W_B);

    const int tid = threadIdx.x;
    const int bt  = blockIdx.x;       // 0..255
    const int chb = blockIdx.y * 64;  // channel base
    const int t   = bt & 7;
    const int y    = tid >> 5;        // warp -> y row (0..13)
    const int lane = tid & 31;        // channel pair within slice

    // ---- stage weights + bias ----
    for (int i = tid; i < 64 * 27; i += CONV_THREADS)
        s_w[i] = __ldg(&cw[(chb + i / 27) * 27 + i % 27]);
    if (tid < 64) s_b[tid] = __ldg(&cb[chb + tid]);

    // ---- stage 3 temporal slabs (cp.async), zero-fill invalid ----
    bool sv[3];
    #pragma unroll
    for (int d = 0; d < 3; ++d) {
        const int tt = t + d - 1;
        sv[d] = ((unsigned)tt < (unsigned)T_);
        uint32_t* slab = s_data + d * SLAB_WORDS;
        if (sv[d]) {
            const __nv_bfloat16* src = g_h + (size_t)(bt + d - 1) * P_ * CA_ + chb;
            for (int i = tid; i < SLAB_WORDS / 4; i += CONV_THREADS) {   // 1568 chunks of 16B
                const int pos = i >> 3;
                const int co  = (i & 7) * 8;            // channel offset (bf16 elems)
                cp16(slab + i * 4, src + (size_t)pos * CA_ + co);
            }
        } else {
            uint4 z = {0u, 0u, 0u, 0u};
            for (int i = tid; i < SLAB_WORDS / 4; i += CONV_THREADS)
                ((uint4*)slab)[i] = z;
        }
    }
    asm volatile("cp.async.commit_group;\n" ::: "memory");
    asm volatile("cp.async.wait_group 0;\n" ::: "memory");
    __syncthreads();

    // ---- per-thread weights from smem ----
    const int c0 = lane * 2;
    float2 wv[27];
    #pragma unroll
    for (int j = 0; j < 27; ++j) {
        wv[j].x = s_w[c0 * 27 + j];
        wv[j].y = s_w[(c0 + 1) * 27 + j];
    }
    const float bx = s_b[c0];
    const float by = s_b[c0 + 1];

    // ---- 9 (dt,dy) row pointers in smem ----
    const uint32_t* lp[9];
    bool rv[9];
    #pragma unroll
    for (int d = 0; d < 3; ++d) {
        #pragma unroll
        for (int dy = -1; dy <= 1; ++dy) {
            const int j = d * 3 + (dy + 1);
            const int y2 = y + dy;
            rv[j] = sv[d] && ((unsigned)y2 < (unsigned)H_);
            lp[j] = s_data + d * SLAB_WORDS + (rv[j] ? y2 : y) * (W_ * 32) + lane;
        }
    }

    uint32_t v0[9], v1[9], v2[9];
    #pragma unroll
    for (int j = 0; j < 9; ++j) {
        v0[j] = 0u;
        v1[j] = rv[j] ? lp[j][0] : 0u;
    }

    uint32_t* gout = (uint32_t*)(g_g + (size_t)(bt * P_ + y * W_) * CA_ + chb) + lane;

    for (int x = 0; x < W_; ++x) {
        const bool in = (x + 1) < W_;
        #pragma unroll
        for (int j = 0; j < 9; ++j)
            v2[j] = (rv[j] && in) ? lp[j][(x + 1) * 32] : 0u;

        float ax = bx, ay = by;
        #pragma unroll
        for (int j = 0; j < 9; ++j) {
            const float2 f0 = __bfloat1622float2(*(const __nv_bfloat162*)&v0[j]);
            const float2 f1 = __bfloat1622float2(*(const __nv_bfloat162*)&v1[j]);
            const float2 f2 = __bfloat1622float2(*(const __nv_bfloat162*)&v2[j]);
            ax = fmaf(wv[3 * j + 0].x, f0.x, ax);
            ay = fmaf(wv[3 * j + 0].y, f0.y, ay);
            ax = fmaf(wv[3 * j + 1].x, f1.x, ax);
            ay = fmaf(wv[3 * j + 1].y, f1.y, ay);
            ax = fmaf(wv[3 * j + 2].x, f2.x, ax);
            ay = fmaf(wv[3 * j + 2].y, f2.y, ay);
        }
        const __nv_bfloat162 r = __floats2bfloat162_rn(ax, ay);
        gout[(size_t)x * (CA_ / 2)] = *(const uint32_t*)&r;

        #pragma unroll
        for (int j = 0; j < 9; ++j) { v0[j] = v1[j]; v1[j] = v2[j]; }
    }
}

// ---------------- launch ----------------
extern "C" void kernel_launch(void* const* d_in, const int* in_sizes, int n_in,
                              void* d_out, int out_size) {
    const float* x      = (const float*)d_in[0];
    const float* W1     = (const float*)d_in[1];
    const float* b1     = (const float*)d_in[2];
    const float* conv_w = (const float*)d_in[3];
    const float* conv_b = (const float*)d_in[4];
    const float* W2     = (const float*)d_in[5];
    const float* b2     = (const float*)d_in[6];
    float* out = (float*)d_out;
    (void)in_sizes; (void)n_in; (void)out_size;

    const int smem_bytes = GSTAGES * GSTAGE_BYTES;  // 81920
    cudaFuncSetAttribute(gemm_k<0>, cudaFuncAttributeMaxDynamicSharedMemorySize, smem_bytes);
    cudaFuncSetAttribute(gemm_k<1>, cudaFuncAttributeMaxDynamicSharedMemorySize, smem_bytes);
    cudaFuncSetAttribute(conv_kernel, cudaFuncAttributeMaxDynamicSharedMemorySize, CONV_SMEM_B);

    prep_weights<<<(CA_ * C_) / 256, 256>>>(W1, W2);
    prep_x<<<(int)(((size_t)M_ * C_ / 4 + 255) / 256), 256>>>((const float4*)x);
    cls_copy<<<(BT_ * C_ / 4) / 256, 256>>>((const float4*)x, (float4*)out);

    gemm_k<0><<<dim3(CA_ / GBN, M_ / GBM), 256, smem_bytes>>>(b1, nullptr, nullptr);

    conv_kernel<<<dim3(BT_, CA_ / 64), CONV_THREADS, CONV_SMEM_B>>>(conv_w, conv_b);

    gemm_k<1><<<dim3(C_ / GBN, M_ / GBM), 256, smem_bytes>>>(b2, x, out);
}